// round 16
// baseline (speedup 1.0000x reference)
#include <cuda_runtime.h>
#include <cuda_fp16.h>
#include <cstdint>

#define EPS_BN 1e-5f
#define NMAX 200000
#define KTOT 27

// ---------------- scratch (no allocations allowed) ----------------
__device__ float g_t1[NMAX * 64];
__device__ float g_t2[NMAX * 64];
__device__ float g_t3[NMAX * 128];
__device__ float g_o1[NMAX * 64];
__device__ float g_t5[NMAX * 128];
__device__ float g_stats[5 * 256];
__device__ float g_ab[5 * 256];
// plain fp16 activation rows
__device__ __half g_x1[NMAX * 256];
__device__ __half g_t1s[NMAX * 64];
__device__ __half g_t2s[NMAX * 64];
__device__ __half g_o1s[NMAX * 64];
// pre-transposed ([cout][cin]) + XOR-swizzled fp16 weights, hi/lo pair
__device__ __half g_w1h[256 * 64],        g_w1l[256 * 64];
__device__ __half g_w2h[KTOT * 64 * 64],  g_w2l[KTOT * 64 * 64];
__device__ __half g_w3h[64 * 128],        g_w3l[64 * 128];
__device__ __half g_w4h[KTOT * 256 * 64], g_w4l[KTOT * 256 * 64];
__device__ __half g_w5h[KTOT * 64 * 128], g_w5l[KTOT * 64 * 128];

// ---------------- primitives ----------------
__device__ __forceinline__ uint32_t smem_u32(const void* p) {
    return (uint32_t)__cvta_generic_to_shared(p);
}
__device__ __forceinline__ void red_add_v4(float* p, float a, float b, float c, float d) {
    asm volatile("red.global.add.v4.f32 [%0], {%1,%2,%3,%4};"
                 :: "l"(p), "f"(a), "f"(b), "f"(c), "f"(d) : "memory");
}
__device__ __forceinline__ void cpasync16(void* dst, const void* src) {
    uint32_t d = smem_u32(dst);
    asm volatile("cp.async.cg.shared.global [%0], [%1], 16;" :: "r"(d), "l"(src) : "memory");
}
#define CP_COMMIT() asm volatile("cp.async.commit_group;" ::: "memory")
#define CP_WAIT(N)  asm volatile("cp.async.wait_group %0;" :: "n"(N) : "memory")

#define MBAR_INIT(mbar, cnt) \
    asm volatile("mbarrier.init.shared.b64 [%0], %1;" :: "r"(mbar), "r"(cnt) : "memory")
#define MBAR_ARRIVE(mbar) \
    asm volatile("mbarrier.arrive.shared.b64 _, [%0];" :: "r"(mbar) : "memory")
#define MBAR_ARRIVE_TX(mbar, bytes) \
    asm volatile("mbarrier.arrive.expect_tx.shared.b64 _, [%0], %1;" :: "r"(mbar), "r"(bytes) : "memory")
#define MBAR_WAIT(mbar, ph) do {                                                     \
    uint32_t _m = (mbar), _p = (ph), _done;                                          \
    asm volatile("{\n\t.reg .pred p;\n\t"                                            \
        "mbarrier.try_wait.parity.acquire.cta.shared::cta.b64 p, [%1], %2;\n\t"      \
        "selp.b32 %0, 1, 0, p;\n\t}"                                                 \
        : "=r"(_done) : "r"(_m), "r"(_p) : "memory");                                \
    if (!_done) {                                                                    \
        asm volatile("{\n\t.reg .pred P1;\n\t"                                       \
            "WL_%=:\n\t"                                                             \
            "mbarrier.try_wait.parity.acquire.cta.shared::cta.b64 P1, [%0], %1, 0x989680;\n\t" \
            "@P1 bra.uni WD_%=;\n\t"                                                 \
            "bra.uni WL_%=;\n\t"                                                     \
            "WD_%=:\n\t}"                                                            \
            :: "r"(_m), "r"(_p) : "memory");                                         \
    }                                                                                \
} while (0)

__device__ __forceinline__ void bulk_ld(uint32_t dst, const void* src, uint32_t bytes, uint32_t mbar) {
    asm volatile("cp.async.bulk.shared::cluster.global.mbarrier::complete_tx::bytes [%0], [%1], %2, [%3];"
                 :: "r"(dst), "l"(src), "r"(bytes), "r"(mbar) : "memory");
}

__device__ __forceinline__ void ldsm_x4(uint32_t (&r)[4], uint32_t addr) {
    asm volatile("ldmatrix.sync.aligned.m8n8.x4.shared.b16 {%0,%1,%2,%3}, [%4];"
                 : "=r"(r[0]), "=r"(r[1]), "=r"(r[2]), "=r"(r[3]) : "r"(addr));
}
__device__ __forceinline__ void mma_f16(float (&d)[4], const uint32_t (&a)[4],
                                        uint32_t b0, uint32_t b1) {
    asm volatile("mma.sync.aligned.m16n8k16.row.col.f32.f16.f16.f32 "
                 "{%0,%1,%2,%3}, {%4,%5,%6,%7}, {%8,%9}, {%0,%1,%2,%3};"
                 : "+f"(d[0]), "+f"(d[1]), "+f"(d[2]), "+f"(d[3])
                 : "r"(a[0]), "r"(a[1]), "r"(a[2]), "r"(a[3]), "r"(b0), "r"(b1));
}

// ---------------- gather(bulk) + fp16 MMA with W hi/lo 2 chains + (scatter|store) ----------------
// src: plain fp16 rows [row][CIN]. One cp.async.bulk per gathered row.
// A smem: padded row stride SROW = 2*CIN+16 -> conflict-free ldsm without swizzle.
// W smem: two [COUT][CIN] fp16 tiles (Wh, Wl), 16B-chunk XOR swizzle (pre-swizzled).
// D = A*Wh + A*Wl. Warp partition generalizes over THREADS/TILE_M.
template<int CIN, int COUT, int TILE_M, int THREADS, bool SPARSE, int MINB, bool STATS>
__global__ void __launch_bounds__(THREADS, MINB)
conv_mma_kernel(const __half* __restrict__ src,
                const __half* __restrict__ WgH,
                const __half* __restrict__ WgL,
                const int* __restrict__ in_idx,
                const int* __restrict__ out_idx,
                int M, int iters,
                float* __restrict__ out,
                float* __restrict__ stats)
{
    constexpr int ROWB = 2 * CIN;
    constexpr int SROW = ROWB + 16;
    constexpr int ABUF = TILE_M * SROW;
    constexpr int CINB = CIN * 2;
    constexpr int WBYT = COUT * CINB;
    constexpr int NW   = THREADS / 32;
    constexpr int MT16 = TILE_M / 16;
    constexpr int NSPLIT = NW / MT16;
    constexpr int WNT = COUT / 8 / NSPLIT;
    constexpr int KS = CIN / 16;

    extern __shared__ char sm[];
    char* A0 = sm;
    char* A1 = sm + ABUF;
    char* WsH = sm + 2 * ABUF;
    char* WsL = WsH + WBYT;
    __shared__ unsigned long long s_mbar[2];
    __shared__ float sred[STATS ? 2 * COUT : 1];

    const int tid = threadIdx.x, wid = tid >> 5, lane = tid & 31;
    const int k = blockIdx.y;
    const char* wkh = (const char*)(WgH + (size_t)k * (CIN * COUT));
    const char* wkl = (const char*)(WgL + (size_t)k * (CIN * COUT));
    const int* inp  = SPARSE ? in_idx  + (size_t)k * M : nullptr;
    const int* outp = SPARSE ? out_idx + (size_t)k * M : nullptr;

    const uint32_t mb[2] = { smem_u32(&s_mbar[0]), smem_u32(&s_mbar[1]) };
    if (tid == 0) { MBAR_INIT(mb[0], TILE_M); MBAR_INIT(mb[1], TILE_M); }
    if (STATS) {
        for (int i = tid; i < 2 * COUT; i += THREADS) sred[i] = 0.f;
    }

    for (int i = tid; i < WBYT / 16; i += THREADS) {
        cpasync16(WsH + i * 16, wkh + i * 16);
        cpasync16(WsL + i * 16, wkl + i * 16);
    }
    CP_COMMIT();
    __syncthreads();

    const long tile0 = (long)blockIdx.x * iters;

    auto gather = [&](char* A, uint32_t mbar, long base) {
        if (tid < TILE_M) {
            long g = base + tid;
            if (g < M) {
                int row = SPARSE ? __ldg(inp + g) : (int)g;
                MBAR_ARRIVE_TX(mbar, (uint32_t)ROWB);
                bulk_ld(smem_u32(A + tid * SROW), (const char*)src + (size_t)row * ROWB,
                        (uint32_t)ROWB, mbar);
            } else {
                MBAR_ARRIVE(mbar);
            }
        }
    };

    gather(A0, mb[0], tile0 * TILE_M);
    CP_WAIT(0);
    __syncthreads();

    const int mrow0 = (wid % MT16) * 16;
    const int nbase = (wid / MT16) * (COUT / NSPLIT);
    const int q = lane >> 3, r = lane & 7;
    const int arow = mrow0 + r + 8 * (q & 1);
    const uint32_t aoff = arow * SROW + 16 * (q >> 1);
    const int brow_loc = r + 8 * (q >> 1);
    const int bksel = q & 1;

    const uint32_t wH_u = smem_u32(WsH), wL_u = smem_u32(WsL);

    float ss[STATS ? 2 * WNT : 1], s2[STATS ? 2 * WNT : 1];
    if (STATS) {
        #pragma unroll
        for (int j = 0; j < 2 * WNT; ++j) { ss[j] = 0.f; s2[j] = 0.f; }
    }

    int ph[2] = {0, 0};

    for (int it = 0; it < iters; ++it) {
        const long bse = (tile0 + it) * (long)TILE_M;
        if (bse >= M) break;
        const int cur = it & 1, nxt = cur ^ 1;
        const bool more = (it + 1 < iters) && ((tile0 + it + 1) * (long)TILE_M < M);
        if (more)
            gather(nxt ? A1 : A0, mb[nxt], (tile0 + it + 1) * (long)TILE_M);

        MBAR_WAIT(mb[cur], ph[cur]);
        ph[cur] ^= 1;

        const uint32_t aBase = smem_u32(cur ? A1 : A0) + aoff;

        float acc[WNT][4];
        #pragma unroll
        for (int j = 0; j < WNT; ++j)
            acc[j][0] = acc[j][1] = acc[j][2] = acc[j][3] = 0.f;

        #pragma unroll
        for (int ks = 0; ks < KS; ++ks) {
            uint32_t aW[4];
            ldsm_x4(aW, aBase + 32 * ks);
            #pragma unroll
            for (int jp = 0; jp < WNT / 2; ++jp) {
                const int wrow = nbase + 16 * jp + brow_loc;
                const uint32_t woff = wrow * CINB + 16 * ((ks * 2 + bksel) ^ (wrow & 7));
                uint32_t bH[4], bL[4];
                ldsm_x4(bH, wH_u + woff);
                mma_f16(acc[2 * jp],     aW, bH[0], bH[1]);
                mma_f16(acc[2 * jp + 1], aW, bH[2], bH[3]);
                ldsm_x4(bL, wL_u + woff);
                mma_f16(acc[2 * jp],     aW, bL[0], bL[1]);
                mma_f16(acc[2 * jp + 1], aW, bL[2], bL[3]);
            }
        }

        // ---- epilogue: shfl-pair into v4 ops ----
        {
            const int grp = lane >> 2, qd = lane & 3;
            const int row0 = mrow0 + grp, row1 = row0 + 8;
            const long g0 = bse + row0, g1 = bse + row1;
            const bool v0 = g0 < M, v1 = g1 < M;
            int or0 = 0, or1 = 0;
            if (v0) or0 = SPARSE ? __ldg(outp + g0) : (int)g0;
            if (v1) or1 = SPARSE ? __ldg(outp + g1) : (int)g1;
            float* p0 = out + (size_t)or0 * COUT;
            float* p1 = out + (size_t)or1 * COUT;
            #pragma unroll
            for (int j = 0; j < WNT; ++j) {
                float a0 = acc[j][0], a1 = acc[j][1], a2 = acc[j][2], a3 = acc[j][3];
                if (STATS) {
                    if (v0) { ss[2*j]   += a0; s2[2*j]   += a0 * a0;
                              ss[2*j+1] += a1; s2[2*j+1] += a1 * a1; }
                    if (v1) { ss[2*j]   += a2; s2[2*j]   += a2 * a2;
                              ss[2*j+1] += a3; s2[2*j+1] += a3 * a3; }
                }
                float b0 = __shfl_xor_sync(0xFFFFFFFFu, a0, 1);
                float b1 = __shfl_xor_sync(0xFFFFFFFFu, a1, 1);
                float b2 = __shfl_xor_sync(0xFFFFFFFFu, a2, 1);
                float b3 = __shfl_xor_sync(0xFFFFFFFFu, a3, 1);
                if (!(qd & 1)) {
                    const int col = nbase + 8 * j + qd * 2;
                    if (SPARSE) {
                        if (v0) red_add_v4(p0 + col, a0, a1, b0, b1);
                        if (v1) red_add_v4(p1 + col, a2, a3, b2, b3);
                    } else {
                        if (v0) *(float4*)(p0 + col) = make_float4(a0, a1, b0, b1);
                        if (v1) *(float4*)(p1 + col) = make_float4(a2, a3, b2, b3);
                    }
                }
            }
        }
        __syncthreads();
    }

    if (STATS) {
        #pragma unroll
        for (int j = 0; j < 2 * WNT; ++j) {
            #pragma unroll
            for (int m = 4; m <= 16; m <<= 1) {
                ss[j] += __shfl_xor_sync(0xFFFFFFFFu, ss[j], m);
                s2[j] += __shfl_xor_sync(0xFFFFFFFFu, s2[j], m);
            }
        }
        const int qd = lane & 3;
        if ((lane >> 2) == 0) {
            #pragma unroll
            for (int j = 0; j < WNT; ++j) {
                const int col = nbase + 8 * j + qd * 2;
                atomicAdd(&sred[col],            ss[2*j]);
                atomicAdd(&sred[col + 1],        ss[2*j+1]);
                atomicAdd(&sred[COUT + col],     s2[2*j]);
                atomicAdd(&sred[COUT + col + 1], s2[2*j+1]);
            }
        }
        __syncthreads();
        for (int i = tid; i < 2 * COUT; i += THREADS)
            atomicAdd(&stats[i], sred[i]);
    }
}

// ---------------- prep: fp32 -> plain fp16 rows ----------------
__global__ void cast_kernel(const float* __restrict__ src, long total4,
                            __half* __restrict__ dst)
{
    for (long i = (long)blockIdx.x * blockDim.x + threadIdx.x; i < total4;
         i += (long)gridDim.x * blockDim.x) {
        float4 v = ((const float4*)src)[i];
        __half2* p = (__half2*)(dst + i * 4);
        p[0] = __halves2half2(__float2half_rn(v.x), __float2half_rn(v.y));
        p[1] = __halves2half2(__float2half_rn(v.z), __float2half_rn(v.w));
    }
}

// weights: [K][CIN][COUT] fp32 -> [cout][cin] fp16 hi/lo, 16B-chunk XOR swizzle
__global__ void wprep_kernel(const float* __restrict__ W, int K, int CIN, int COUT,
                             __half* __restrict__ wh, __half* __restrict__ wl)
{
    long total = (long)K * CIN * COUT;
    for (long i = (long)blockIdx.x * blockDim.x + threadIdx.x; i < total;
         i += (long)gridDim.x * blockDim.x) {
        int k = (int)(i / (CIN * COUT));
        int rr = (int)(i % (CIN * COUT));
        int cin = rr / COUT, cout = rr % COUT;
        float v = W[i];
        __half h = __float2half_rn(v);
        __half l = __float2half_rn(v - __half2float(h));
        int off = cout * CIN * 2 + 16 * ((cin >> 3) ^ (cout & 7)) + (cin & 7) * 2;
        char* bh = (char*)wh + (size_t)k * (CIN * COUT * 2);
        char* bl = (char*)wl + (size_t)k * (CIN * COUT * 2);
        *(__half*)(bh + off) = h;
        *(__half*)(bl + off) = l;
    }
}

// ---------------- BN ----------------
template<int C_>
__global__ void bnstat_kernel(const float* __restrict__ t, int n, float* __restrict__ stats)
{
    constexpr int RPB = 256 / C_;
    const int c = threadIdx.x & (C_ - 1);
    const int sub = threadIdx.x / C_;
    float s = 0.f, s2 = 0.f;
    for (long r = (long)blockIdx.x * RPB + sub; r < n; r += (long)gridDim.x * RPB) {
        float v = t[r * C_ + c];
        s += v; s2 += v * v;
    }
    atomicAdd(&stats[c], s);
    atomicAdd(&stats[C_ + c], s2);
}

__global__ void bn_finalize_kernel(const float* __restrict__ stats,
                                   const float* __restrict__ g,
                                   const float* __restrict__ be,
                                   float invN, int C_, float* __restrict__ ab)
{
    int c = threadIdx.x;
    if (c < C_) {
        float mean = stats[c] * invN;
        float var = stats[C_ + c] * invN - mean * mean;
        float a = g[c] * rsqrtf(var + EPS_BN);
        ab[c] = a;
        ab[C_ + c] = be[c] - mean * a;
    }
}

// y = relu(a*x + s) -> plain fp16 rows for the next conv
template<int C_>
__global__ void bn_apply_h_kernel(const float* __restrict__ t, long n,
                                  const float* __restrict__ ab,
                                  __half* __restrict__ dst)
{
    const long total4 = n * (C_ / 4);
    for (long i = (long)blockIdx.x * blockDim.x + threadIdx.x; i < total4;
         i += (long)gridDim.x * blockDim.x) {
        int c = ((int)(i % (C_ / 4))) * 4;
        float4 v = ((const float4*)t)[i];
        float r0 = fmaxf(v.x * ab[c]     + ab[C_ + c],     0.f);
        float r1 = fmaxf(v.y * ab[c + 1] + ab[C_ + c + 1], 0.f);
        float r2 = fmaxf(v.z * ab[c + 2] + ab[C_ + c + 2], 0.f);
        float r3 = fmaxf(v.w * ab[c + 3] + ab[C_ + c + 3], 0.f);
        __half2* p = (__half2*)(dst + i * 4);
        p[0] = __halves2half2(__float2half_rn(r0), __float2half_rn(r1));
        p[1] = __halves2half2(__float2half_rn(r2), __float2half_rn(r3));
    }
}

__global__ void final_kernel(const float* __restrict__ x,
                             const float* __restrict__ t3,
                             const float* __restrict__ t5,
                             const float* __restrict__ ab3,
                             const float* __restrict__ ab5,
                             float* __restrict__ out, long n)
{
    const long total4 = n * 64;
    for (long i = (long)blockIdx.x * blockDim.x + threadIdx.x; i < total4;
         i += (long)gridDim.x * blockDim.x) {
        long row = i >> 6;
        int c4 = ((int)i & 63) * 4;
        float4 xv = ((const float4*)x)[i];
        float4 tv; const float* ab; int c;
        if (c4 < 128) { tv = *(const float4*)(t3 + row * 128 + c4);         ab = ab3; c = c4; }
        else          { tv = *(const float4*)(t5 + row * 128 + (c4 - 128)); ab = ab5; c = c4 - 128; }
        float4 r;
        r.x = fmaxf(tv.x * ab[c]     + ab[128 + c],     0.f) + xv.x;
        r.y = fmaxf(tv.y * ab[c + 1] + ab[128 + c + 1], 0.f) + xv.y;
        r.z = fmaxf(tv.z * ab[c + 2] + ab[128 + c + 2], 0.f) + xv.z;
        r.w = fmaxf(tv.w * ab[c + 3] + ab[128 + c + 3], 0.f) + xv.w;
        ((float4*)out)[i] = r;
    }
}

// ---------------- launch ----------------
// smem: 2*TILE_M*(2CIN+16) + 2*COUT*2CIN
static constexpr int S_256_128 = 2 * (128 * 528) + 2 * (64 * 512);   // 200704, 1 CTA/SM
static constexpr int S_64_256a = 2 * (256 * 144) + 2 * (64 * 128);   // 90112  (conv2)
static constexpr int S_64_256b = 2 * (256 * 144) + 2 * (128 * 128);  // 106496 (conv5)
static constexpr int S_64_128  = 2 * (128 * 144) + 2 * (128 * 128);  // 69632  (conv3, 2 CTA/SM)

extern "C" void kernel_launch(void* const* d_in, const int* in_sizes, int n_in,
                              void* d_out, int out_size)
{
    const float* x      = (const float*)d_in[0];
    const int*   in_idx = (const int*)d_in[1];
    const int*   out_idx= (const int*)d_in[2];
    const float* W1 = (const float*)d_in[3];
    const float* g1 = (const float*)d_in[5];
    const float* be1= (const float*)d_in[6];
    const float* W2 = (const float*)d_in[7];
    const float* g2 = (const float*)d_in[9];
    const float* be2= (const float*)d_in[10];
    const float* W3 = (const float*)d_in[11];
    const float* g3 = (const float*)d_in[13];
    const float* be3= (const float*)d_in[14];
    const float* W4 = (const float*)d_in[15];
    const float* g4 = (const float*)d_in[17];
    const float* be4= (const float*)d_in[18];
    const float* W5 = (const float*)d_in[19];
    const float* g5 = (const float*)d_in[21];
    const float* be5= (const float*)d_in[22];
    // biases b1..b5 cancel under training-mode BN.

    const int n = in_sizes[0] / 256;
    const int M = in_sizes[1] / 27;
    float* out = (float*)d_out;

    float *t1, *t2, *t3, *o1, *t5, *stats, *ab;
    cudaGetSymbolAddress((void**)&t1, g_t1);
    cudaGetSymbolAddress((void**)&t2, g_t2);
    cudaGetSymbolAddress((void**)&t3, g_t3);
    cudaGetSymbolAddress((void**)&o1, g_o1);
    cudaGetSymbolAddress((void**)&t5, g_t5);
    cudaGetSymbolAddress((void**)&stats, g_stats);
    cudaGetSymbolAddress((void**)&ab, g_ab);
    __half *x1, *t1s, *t2s, *o1s;
    __half *w1h,*w1l,*w2h,*w2l,*w3h,*w3l,*w4h,*w4l,*w5h,*w5l;
    cudaGetSymbolAddress((void**)&x1,  g_x1);
    cudaGetSymbolAddress((void**)&t1s, g_t1s);
    cudaGetSymbolAddress((void**)&t2s, g_t2s);
    cudaGetSymbolAddress((void**)&o1s, g_o1s);
    cudaGetSymbolAddress((void**)&w1h, g_w1h); cudaGetSymbolAddress((void**)&w1l, g_w1l);
    cudaGetSymbolAddress((void**)&w2h, g_w2h); cudaGetSymbolAddress((void**)&w2l, g_w2l);
    cudaGetSymbolAddress((void**)&w3h, g_w3h); cudaGetSymbolAddress((void**)&w3l, g_w3l);
    cudaGetSymbolAddress((void**)&w4h, g_w4h); cudaGetSymbolAddress((void**)&w4l, g_w4l);
    cudaGetSymbolAddress((void**)&w5h, g_w5h); cudaGetSymbolAddress((void**)&w5l, g_w5l);

    cudaFuncSetAttribute((const void*)conv_mma_kernel<256, 64, 128, 512, false, 1, true >, cudaFuncAttributeMaxDynamicSharedMemorySize, S_256_128);
    cudaFuncSetAttribute((const void*)conv_mma_kernel<256, 64, 128, 512, true,  1, false>, cudaFuncAttributeMaxDynamicSharedMemorySize, S_256_128);
    cudaFuncSetAttribute((const void*)conv_mma_kernel<64,  64, 256, 512, true,  1, false>, cudaFuncAttributeMaxDynamicSharedMemorySize, S_64_256a);
    cudaFuncSetAttribute((const void*)conv_mma_kernel<64, 128, 128, 256, false, 2, true >, cudaFuncAttributeMaxDynamicSharedMemorySize, S_64_128);
    cudaFuncSetAttribute((const void*)conv_mma_kernel<64, 128, 256, 512, true,  1, false>, cudaFuncAttributeMaxDynamicSharedMemorySize, S_64_256b);

    // static side stream + events for the capture fork (host resources, created once)
    static cudaStream_t s1 = nullptr;
    static cudaEvent_t evX = nullptr, evB2 = nullptr;
    if (s1 == nullptr) {
        cudaStreamCreateWithFlags(&s1, cudaStreamNonBlocking);
        cudaEventCreateWithFlags(&evX, cudaEventDisableTiming);
        cudaEventCreateWithFlags(&evB2, cudaEventDisableTiming);
    }

    const float invN = 1.f / (float)n;
    const int ITERS = 8;
    const int ITERS_S256 = 4;   // sparse CIN=64 convs use 256-row tiles: 4 iters = 1024 rows/CTA
    const int gx_n128c = ((n + 127) / 128 + ITERS - 1) / ITERS;
    const int gx_n128 = ((n + 127) / 128 + ITERS - 1) / ITERS;
    const int gx_m128c = ((M + 127) / 128 + ITERS - 1) / ITERS;
    const int gx_m256 = ((M + 255) / 256 + ITERS_S256 - 1) / ITERS_S256;

    // ===== stream s1: branch-2 prep with NO dependency on the cast head =====
    cudaMemsetAsync(o1, 0, (size_t)n * 64 * sizeof(float), s1);
    cudaMemsetAsync(t5, 0, (size_t)n * 128 * sizeof(float), s1);
    wprep_kernel<<<1728, 256, 0, s1>>>(W4, KTOT, 256, 64, w4h, w4l);
    wprep_kernel<<<864, 256, 0, s1>>>(W5, KTOT, 64, 128, w5h, w5l);

    // ===== stream 0 head: shared prep =====
    cudaMemsetAsync(stats, 0, 5 * 256 * sizeof(float), 0);
    cudaMemsetAsync(t2, 0, (size_t)n * 64 * sizeof(float), 0);
    wprep_kernel<<<64, 256, 0, 0>>>(W1, 1, 256, 64, w1h, w1l);
    wprep_kernel<<<432, 256, 0, 0>>>(W2, KTOT, 64, 64, w2h, w2l);
    wprep_kernel<<<32, 256, 0, 0>>>(W3, 1, 64, 128, w3h, w3l);
    cast_kernel<<<2048, 256, 0, 0>>>(x, (long)n * 64, x1);
    cudaEventRecord(evX, 0);

    // ===== stream s1: branch 2 (conv4 -> conv5) =====
    cudaStreamWaitEvent(s1, evX, 0);
    conv_mma_kernel<256, 64, 128, 512, true, 1, false><<<dim3(gx_m128c, 27), 512, S_256_128, s1>>>(
        x1, w4h, w4l, in_idx, out_idx, M, ITERS, o1, nullptr);
    bnstat_kernel<64><<<512, 256, 0, s1>>>(o1, n, stats + 768);
    bn_finalize_kernel<<<1, 64, 0, s1>>>(stats + 768, g4, be4, invN, 64, ab + 768);
    bn_apply_h_kernel<64><<<1024, 256, 0, s1>>>(o1, (long)n, ab + 768, o1s);
    conv_mma_kernel<64, 128, 256, 512, true, 1, false><<<dim3(gx_m256, 27), 512, S_64_256b, s1>>>(
        o1s, w5h, w5l, in_idx, out_idx, M, ITERS_S256, t5, nullptr);
    bnstat_kernel<128><<<512, 256, 0, s1>>>(t5, n, stats + 1024);
    bn_finalize_kernel<<<1, 128, 0, s1>>>(stats + 1024, g5, be5, invN, 128, ab + 1024);
    cudaEventRecord(evB2, s1);

    // ===== stream 0: branch 1 (conv1 -> conv2 -> conv3) =====
    conv_mma_kernel<256, 64, 128, 512, false, 1, true><<<dim3(gx_n128c, 1), 512, S_256_128, 0>>>(
        x1, w1h, w1l, nullptr, nullptr, n, ITERS, t1, stats);
    bn_finalize_kernel<<<1, 64, 0, 0>>>(stats, g1, be1, invN, 64, ab);
    bn_apply_h_kernel<64><<<1024, 256, 0, 0>>>(t1, (long)n, ab, t1s);
    conv_mma_kernel<64, 64, 256, 512, true, 1, false><<<dim3(gx_m256, 27), 512, S_64_256a, 0>>>(
        t1s, w2h, w2l, in_idx, out_idx, M, ITERS_S256, t2, nullptr);
    bnstat_kernel<64><<<512, 256, 0, 0>>>(t2, n, stats + 256);
    bn_finalize_kernel<<<1, 64, 0, 0>>>(stats + 256, g2, be2, invN, 64, ab + 256);
    bn_apply_h_kernel<64><<<1024, 256, 0, 0>>>(t2, (long)n, ab + 256, t2s);
    conv_mma_kernel<64, 128, 128, 256, false, 2, true><<<dim3(gx_n128, 1), 256, S_64_128, 0>>>(
        t2s, w3h, w3l, nullptr, nullptr, n, ITERS, t3, stats + 512);
    bn_finalize_kernel<<<1, 128, 0, 0>>>(stats + 512, g3, be3, invN, 128, ab + 512);

    // ===== join + final =====
    cudaStreamWaitEvent(0, evB2, 0);
    final_kernel<<<1024, 256, 0, 0>>>(x, t3, t5, ab + 512, ab + 1024, out, (long)n);
}

// round 17
// speedup vs baseline: 1.0531x; 1.0531x over previous
#include <cuda_runtime.h>
#include <cuda_fp16.h>
#include <cstdint>

#define EPS_BN 1e-5f
#define NMAX 200000
#define KTOT 27

// ---------------- scratch (no allocations allowed) ----------------
__device__ float g_t1[NMAX * 64];
__device__ float g_t2[NMAX * 64];
__device__ float g_t3[NMAX * 128];
__device__ float g_o1[NMAX * 64];
__device__ float g_t5[NMAX * 128];
__device__ float g_stats[5 * 256];
__device__ float g_ab[5 * 256];
// plain fp16 activation rows
__device__ __half g_x1[NMAX * 256];
__device__ __half g_t1s[NMAX * 64];
__device__ __half g_t2s[NMAX * 64];
__device__ __half g_o1s[NMAX * 64];
// pre-transposed ([cout][cin]) + XOR-swizzled fp16 weights, hi/lo pair
__device__ __half g_w1h[256 * 64],        g_w1l[256 * 64];
__device__ __half g_w2h[KTOT * 64 * 64],  g_w2l[KTOT * 64 * 64];
__device__ __half g_w3h[64 * 128],        g_w3l[64 * 128];
__device__ __half g_w4h[KTOT * 256 * 64], g_w4l[KTOT * 256 * 64];
__device__ __half g_w5h[KTOT * 64 * 128], g_w5l[KTOT * 64 * 128];

// ---------------- primitives ----------------
__device__ __forceinline__ uint32_t smem_u32(const void* p) {
    return (uint32_t)__cvta_generic_to_shared(p);
}
__device__ __forceinline__ void red_add_v4(float* p, float a, float b, float c, float d) {
    asm volatile("red.global.add.v4.f32 [%0], {%1,%2,%3,%4};"
                 :: "l"(p), "f"(a), "f"(b), "f"(c), "f"(d) : "memory");
}
__device__ __forceinline__ void cpasync16(void* dst, const void* src) {
    uint32_t d = smem_u32(dst);
    asm volatile("cp.async.cg.shared.global [%0], [%1], 16;" :: "r"(d), "l"(src) : "memory");
}
#define CP_COMMIT() asm volatile("cp.async.commit_group;" ::: "memory")
#define CP_WAIT(N)  asm volatile("cp.async.wait_group %0;" :: "n"(N) : "memory")

#define MBAR_INIT(mbar, cnt) \
    asm volatile("mbarrier.init.shared.b64 [%0], %1;" :: "r"(mbar), "r"(cnt) : "memory")
#define MBAR_ARRIVE(mbar) \
    asm volatile("mbarrier.arrive.shared.b64 _, [%0];" :: "r"(mbar) : "memory")
#define MBAR_ARRIVE_TX(mbar, bytes) \
    asm volatile("mbarrier.arrive.expect_tx.shared.b64 _, [%0], %1;" :: "r"(mbar), "r"(bytes) : "memory")
#define MBAR_WAIT(mbar, ph) do {                                                     \
    uint32_t _m = (mbar), _p = (ph), _done;                                          \
    asm volatile("{\n\t.reg .pred p;\n\t"                                            \
        "mbarrier.try_wait.parity.acquire.cta.shared::cta.b64 p, [%1], %2;\n\t"      \
        "selp.b32 %0, 1, 0, p;\n\t}"                                                 \
        : "=r"(_done) : "r"(_m), "r"(_p) : "memory");                                \
    if (!_done) {                                                                    \
        asm volatile("{\n\t.reg .pred P1;\n\t"                                       \
            "WL_%=:\n\t"                                                             \
            "mbarrier.try_wait.parity.acquire.cta.shared::cta.b64 P1, [%0], %1, 0x989680;\n\t" \
            "@P1 bra.uni WD_%=;\n\t"                                                 \
            "bra.uni WL_%=;\n\t"                                                     \
            "WD_%=:\n\t}"                                                            \
            :: "r"(_m), "r"(_p) : "memory");                                         \
    }                                                                                \
} while (0)

__device__ __forceinline__ void bulk_ld(uint32_t dst, const void* src, uint32_t bytes, uint32_t mbar) {
    asm volatile("cp.async.bulk.shared::cluster.global.mbarrier::complete_tx::bytes [%0], [%1], %2, [%3];"
                 :: "r"(dst), "l"(src), "r"(bytes), "r"(mbar) : "memory");
}

__device__ __forceinline__ void ldsm_x4(uint32_t (&r)[4], uint32_t addr) {
    asm volatile("ldmatrix.sync.aligned.m8n8.x4.shared.b16 {%0,%1,%2,%3}, [%4];"
                 : "=r"(r[0]), "=r"(r[1]), "=r"(r[2]), "=r"(r[3]) : "r"(addr));
}
__device__ __forceinline__ void mma_f16(float (&d)[4], const uint32_t (&a)[4],
                                        uint32_t b0, uint32_t b1) {
    asm volatile("mma.sync.aligned.m16n8k16.row.col.f32.f16.f16.f32 "
                 "{%0,%1,%2,%3}, {%4,%5,%6,%7}, {%8,%9}, {%0,%1,%2,%3};"
                 : "+f"(d[0]), "+f"(d[1]), "+f"(d[2]), "+f"(d[3])
                 : "r"(a[0]), "r"(a[1]), "r"(a[2]), "r"(a[3]), "r"(b0), "r"(b1));
}

// ---------------- gather(bulk) + fp16 MMA with W hi/lo 2 chains + (scatter|store) ----------------
// src: plain fp16 rows [row][CIN]. One cp.async.bulk per gathered row.
// A smem: padded row stride SROW = 2*CIN+16 -> conflict-free ldsm without swizzle.
// W smem: two [COUT][CIN] fp16 tiles (Wh, Wl), 16B-chunk XOR swizzle (pre-swizzled).
// D = A*Wh + A*Wl. Warp partition generalizes over THREADS/TILE_M.
template<int CIN, int COUT, int TILE_M, int THREADS, bool SPARSE, int MINB, bool STATS>
__global__ void __launch_bounds__(THREADS, MINB)
conv_mma_kernel(const __half* __restrict__ src,
                const __half* __restrict__ WgH,
                const __half* __restrict__ WgL,
                const int* __restrict__ in_idx,
                const int* __restrict__ out_idx,
                int M, int iters,
                float* __restrict__ out,
                float* __restrict__ stats)
{
    constexpr int ROWB = 2 * CIN;
    constexpr int SROW = ROWB + 16;
    constexpr int ABUF = TILE_M * SROW;
    constexpr int CINB = CIN * 2;
    constexpr int WBYT = COUT * CINB;
    constexpr int NW   = THREADS / 32;
    constexpr int MT16 = TILE_M / 16;
    constexpr int NSPLIT = NW / MT16;
    constexpr int WNT = COUT / 8 / NSPLIT;
    constexpr int KS = CIN / 16;

    extern __shared__ char sm[];
    char* A0 = sm;
    char* A1 = sm + ABUF;
    char* WsH = sm + 2 * ABUF;
    char* WsL = WsH + WBYT;
    __shared__ unsigned long long s_mbar[2];
    __shared__ float sred[STATS ? 2 * COUT : 1];

    const int tid = threadIdx.x, wid = tid >> 5, lane = tid & 31;
    const int k = blockIdx.y;
    const char* wkh = (const char*)(WgH + (size_t)k * (CIN * COUT));
    const char* wkl = (const char*)(WgL + (size_t)k * (CIN * COUT));
    const int* inp  = SPARSE ? in_idx  + (size_t)k * M : nullptr;
    const int* outp = SPARSE ? out_idx + (size_t)k * M : nullptr;

    const uint32_t mb[2] = { smem_u32(&s_mbar[0]), smem_u32(&s_mbar[1]) };
    if (tid == 0) { MBAR_INIT(mb[0], TILE_M); MBAR_INIT(mb[1], TILE_M); }
    if (STATS) {
        for (int i = tid; i < 2 * COUT; i += THREADS) sred[i] = 0.f;
    }

    for (int i = tid; i < WBYT / 16; i += THREADS) {
        cpasync16(WsH + i * 16, wkh + i * 16);
        cpasync16(WsL + i * 16, wkl + i * 16);
    }
    CP_COMMIT();
    __syncthreads();

    const long tile0 = (long)blockIdx.x * iters;

    auto gather = [&](char* A, uint32_t mbar, long base) {
        if (tid < TILE_M) {
            long g = base + tid;
            if (g < M) {
                int row = SPARSE ? __ldg(inp + g) : (int)g;
                MBAR_ARRIVE_TX(mbar, (uint32_t)ROWB);
                bulk_ld(smem_u32(A + tid * SROW), (const char*)src + (size_t)row * ROWB,
                        (uint32_t)ROWB, mbar);
            } else {
                MBAR_ARRIVE(mbar);
            }
        }
    };

    gather(A0, mb[0], tile0 * TILE_M);
    CP_WAIT(0);
    __syncthreads();

    const int mrow0 = (wid % MT16) * 16;
    const int nbase = (wid / MT16) * (COUT / NSPLIT);
    const int q = lane >> 3, r = lane & 7;
    const int arow = mrow0 + r + 8 * (q & 1);
    const uint32_t aoff = arow * SROW + 16 * (q >> 1);
    const int brow_loc = r + 8 * (q >> 1);
    const int bksel = q & 1;

    const uint32_t wH_u = smem_u32(WsH), wL_u = smem_u32(WsL);

    float ss[STATS ? 2 * WNT : 1], s2[STATS ? 2 * WNT : 1];
    if (STATS) {
        #pragma unroll
        for (int j = 0; j < 2 * WNT; ++j) { ss[j] = 0.f; s2[j] = 0.f; }
    }

    int ph[2] = {0, 0};

    for (int it = 0; it < iters; ++it) {
        const long bse = (tile0 + it) * (long)TILE_M;
        if (bse >= M) break;
        const int cur = it & 1, nxt = cur ^ 1;
        const bool more = (it + 1 < iters) && ((tile0 + it + 1) * (long)TILE_M < M);
        if (more)
            gather(nxt ? A1 : A0, mb[nxt], (tile0 + it + 1) * (long)TILE_M);

        MBAR_WAIT(mb[cur], ph[cur]);
        ph[cur] ^= 1;

        const uint32_t aBase = smem_u32(cur ? A1 : A0) + aoff;

        float acc[WNT][4];
        #pragma unroll
        for (int j = 0; j < WNT; ++j)
            acc[j][0] = acc[j][1] = acc[j][2] = acc[j][3] = 0.f;

        #pragma unroll
        for (int ks = 0; ks < KS; ++ks) {
            uint32_t aW[4];
            ldsm_x4(aW, aBase + 32 * ks);
            #pragma unroll
            for (int jp = 0; jp < WNT / 2; ++jp) {
                const int wrow = nbase + 16 * jp + brow_loc;
                const uint32_t woff = wrow * CINB + 16 * ((ks * 2 + bksel) ^ (wrow & 7));
                uint32_t bH[4], bL[4];
                ldsm_x4(bH, wH_u + woff);
                mma_f16(acc[2 * jp],     aW, bH[0], bH[1]);
                mma_f16(acc[2 * jp + 1], aW, bH[2], bH[3]);
                ldsm_x4(bL, wL_u + woff);
                mma_f16(acc[2 * jp],     aW, bL[0], bL[1]);
                mma_f16(acc[2 * jp + 1], aW, bL[2], bL[3]);
            }
        }

        // ---- epilogue: shfl-pair into v4 ops ----
        {
            const int grp = lane >> 2, qd = lane & 3;
            const int row0 = mrow0 + grp, row1 = row0 + 8;
            const long g0 = bse + row0, g1 = bse + row1;
            const bool v0 = g0 < M, v1 = g1 < M;
            int or0 = 0, or1 = 0;
            if (v0) or0 = SPARSE ? __ldg(outp + g0) : (int)g0;
            if (v1) or1 = SPARSE ? __ldg(outp + g1) : (int)g1;
            float* p0 = out + (size_t)or0 * COUT;
            float* p1 = out + (size_t)or1 * COUT;
            #pragma unroll
            for (int j = 0; j < WNT; ++j) {
                float a0 = acc[j][0], a1 = acc[j][1], a2 = acc[j][2], a3 = acc[j][3];
                if (STATS) {
                    if (v0) { ss[2*j]   += a0; s2[2*j]   += a0 * a0;
                              ss[2*j+1] += a1; s2[2*j+1] += a1 * a1; }
                    if (v1) { ss[2*j]   += a2; s2[2*j]   += a2 * a2;
                              ss[2*j+1] += a3; s2[2*j+1] += a3 * a3; }
                }
                float b0 = __shfl_xor_sync(0xFFFFFFFFu, a0, 1);
                float b1 = __shfl_xor_sync(0xFFFFFFFFu, a1, 1);
                float b2 = __shfl_xor_sync(0xFFFFFFFFu, a2, 1);
                float b3 = __shfl_xor_sync(0xFFFFFFFFu, a3, 1);
                if (!(qd & 1)) {
                    const int col = nbase + 8 * j + qd * 2;
                    if (SPARSE) {
                        if (v0) red_add_v4(p0 + col, a0, a1, b0, b1);
                        if (v1) red_add_v4(p1 + col, a2, a3, b2, b3);
                    } else {
                        if (v0) *(float4*)(p0 + col) = make_float4(a0, a1, b0, b1);
                        if (v1) *(float4*)(p1 + col) = make_float4(a2, a3, b2, b3);
                    }
                }
            }
        }
        __syncthreads();
    }

    if (STATS) {
        #pragma unroll
        for (int j = 0; j < 2 * WNT; ++j) {
            #pragma unroll
            for (int m = 4; m <= 16; m <<= 1) {
                ss[j] += __shfl_xor_sync(0xFFFFFFFFu, ss[j], m);
                s2[j] += __shfl_xor_sync(0xFFFFFFFFu, s2[j], m);
            }
        }
        const int qd = lane & 3;
        if ((lane >> 2) == 0) {
            #pragma unroll
            for (int j = 0; j < WNT; ++j) {
                const int col = nbase + 8 * j + qd * 2;
                atomicAdd(&sred[col],            ss[2*j]);
                atomicAdd(&sred[col + 1],        ss[2*j+1]);
                atomicAdd(&sred[COUT + col],     s2[2*j]);
                atomicAdd(&sred[COUT + col + 1], s2[2*j+1]);
            }
        }
        __syncthreads();
        for (int i = tid; i < 2 * COUT; i += THREADS)
            atomicAdd(&stats[i], sred[i]);
    }
}

// ---------------- prep: fp32 -> plain fp16 rows ----------------
__global__ void cast_kernel(const float* __restrict__ src, long total4,
                            __half* __restrict__ dst)
{
    for (long i = (long)blockIdx.x * blockDim.x + threadIdx.x; i < total4;
         i += (long)gridDim.x * blockDim.x) {
        float4 v = ((const float4*)src)[i];
        __half2* p = (__half2*)(dst + i * 4);
        p[0] = __halves2half2(__float2half_rn(v.x), __float2half_rn(v.y));
        p[1] = __halves2half2(__float2half_rn(v.z), __float2half_rn(v.w));
    }
}

// weights: [K][CIN][COUT] fp32 -> [cout][cin] fp16 hi/lo, 16B-chunk XOR swizzle
__global__ void wprep_kernel(const float* __restrict__ W, int K, int CIN, int COUT,
                             __half* __restrict__ wh, __half* __restrict__ wl)
{
    long total = (long)K * CIN * COUT;
    for (long i = (long)blockIdx.x * blockDim.x + threadIdx.x; i < total;
         i += (long)gridDim.x * blockDim.x) {
        int k = (int)(i / (CIN * COUT));
        int rr = (int)(i % (CIN * COUT));
        int cin = rr / COUT, cout = rr % COUT;
        float v = W[i];
        __half h = __float2half_rn(v);
        __half l = __float2half_rn(v - __half2float(h));
        int off = cout * CIN * 2 + 16 * ((cin >> 3) ^ (cout & 7)) + (cin & 7) * 2;
        char* bh = (char*)wh + (size_t)k * (CIN * COUT * 2);
        char* bl = (char*)wl + (size_t)k * (CIN * COUT * 2);
        *(__half*)(bh + off) = h;
        *(__half*)(bl + off) = l;
    }
}

// ---------------- BN ----------------
template<int C_>
__global__ void bnstat_kernel(const float* __restrict__ t, int n, float* __restrict__ stats)
{
    constexpr int RPB = 256 / C_;
    const int c = threadIdx.x & (C_ - 1);
    const int sub = threadIdx.x / C_;
    float s = 0.f, s2 = 0.f;
    for (long r = (long)blockIdx.x * RPB + sub; r < n; r += (long)gridDim.x * RPB) {
        float v = t[r * C_ + c];
        s += v; s2 += v * v;
    }
    atomicAdd(&stats[c], s);
    atomicAdd(&stats[C_ + c], s2);
}

__global__ void bn_finalize_kernel(const float* __restrict__ stats,
                                   const float* __restrict__ g,
                                   const float* __restrict__ be,
                                   float invN, int C_, float* __restrict__ ab)
{
    int c = threadIdx.x;
    if (c < C_) {
        float mean = stats[c] * invN;
        float var = stats[C_ + c] * invN - mean * mean;
        float a = g[c] * rsqrtf(var + EPS_BN);
        ab[c] = a;
        ab[C_ + c] = be[c] - mean * a;
    }
}

// y = relu(a*x + s) -> plain fp16 rows for the next conv
template<int C_>
__global__ void bn_apply_h_kernel(const float* __restrict__ t, long n,
                                  const float* __restrict__ ab,
                                  __half* __restrict__ dst)
{
    const long total4 = n * (C_ / 4);
    for (long i = (long)blockIdx.x * blockDim.x + threadIdx.x; i < total4;
         i += (long)gridDim.x * blockDim.x) {
        int c = ((int)(i % (C_ / 4))) * 4;
        float4 v = ((const float4*)t)[i];
        float r0 = fmaxf(v.x * ab[c]     + ab[C_ + c],     0.f);
        float r1 = fmaxf(v.y * ab[c + 1] + ab[C_ + c + 1], 0.f);
        float r2 = fmaxf(v.z * ab[c + 2] + ab[C_ + c + 2], 0.f);
        float r3 = fmaxf(v.w * ab[c + 3] + ab[C_ + c + 3], 0.f);
        __half2* p = (__half2*)(dst + i * 4);
        p[0] = __halves2half2(__float2half_rn(r0), __float2half_rn(r1));
        p[1] = __halves2half2(__float2half_rn(r2), __float2half_rn(r3));
    }
}

__global__ void final_kernel(const float* __restrict__ x,
                             const float* __restrict__ t3,
                             const float* __restrict__ t5,
                             const float* __restrict__ ab3,
                             const float* __restrict__ ab5,
                             float* __restrict__ out, long n)
{
    const long total4 = n * 64;
    for (long i = (long)blockIdx.x * blockDim.x + threadIdx.x; i < total4;
         i += (long)gridDim.x * blockDim.x) {
        long row = i >> 6;
        int c4 = ((int)i & 63) * 4;
        float4 xv = ((const float4*)x)[i];
        float4 tv; const float* ab; int c;
        if (c4 < 128) { tv = *(const float4*)(t3 + row * 128 + c4);         ab = ab3; c = c4; }
        else          { tv = *(const float4*)(t5 + row * 128 + (c4 - 128)); ab = ab5; c = c4 - 128; }
        float4 r;
        r.x = fmaxf(tv.x * ab[c]     + ab[128 + c],     0.f) + xv.x;
        r.y = fmaxf(tv.y * ab[c + 1] + ab[128 + c + 1], 0.f) + xv.y;
        r.z = fmaxf(tv.z * ab[c + 2] + ab[128 + c + 2], 0.f) + xv.z;
        r.w = fmaxf(tv.w * ab[c + 3] + ab[128 + c + 3], 0.f) + xv.w;
        ((float4*)out)[i] = r;
    }
}

// ---------------- launch ----------------
// smem: 2*TILE_M*(2CIN+16) + 2*COUT*2CIN
static constexpr int S_256_128 = 2 * (128 * 528) + 2 * (64 * 512);   // 200704, 1 CTA/SM
static constexpr int S_64_64   = 2 * (128 * 144) + 2 * (64 * 128);   // 53248,  2 CTA/SM
static constexpr int S_64_128  = 2 * (128 * 144) + 2 * (128 * 128);  // 69632,  2 CTA/SM

extern "C" void kernel_launch(void* const* d_in, const int* in_sizes, int n_in,
                              void* d_out, int out_size)
{
    const float* x      = (const float*)d_in[0];
    const int*   in_idx = (const int*)d_in[1];
    const int*   out_idx= (const int*)d_in[2];
    const float* W1 = (const float*)d_in[3];
    const float* g1 = (const float*)d_in[5];
    const float* be1= (const float*)d_in[6];
    const float* W2 = (const float*)d_in[7];
    const float* g2 = (const float*)d_in[9];
    const float* be2= (const float*)d_in[10];
    const float* W3 = (const float*)d_in[11];
    const float* g3 = (const float*)d_in[13];
    const float* be3= (const float*)d_in[14];
    const float* W4 = (const float*)d_in[15];
    const float* g4 = (const float*)d_in[17];
    const float* be4= (const float*)d_in[18];
    const float* W5 = (const float*)d_in[19];
    const float* g5 = (const float*)d_in[21];
    const float* be5= (const float*)d_in[22];
    // biases b1..b5 cancel under training-mode BN.

    const int n = in_sizes[0] / 256;
    const int M = in_sizes[1] / 27;
    float* out = (float*)d_out;

    float *t1, *t2, *t3, *o1, *t5, *stats, *ab;
    cudaGetSymbolAddress((void**)&t1, g_t1);
    cudaGetSymbolAddress((void**)&t2, g_t2);
    cudaGetSymbolAddress((void**)&t3, g_t3);
    cudaGetSymbolAddress((void**)&o1, g_o1);
    cudaGetSymbolAddress((void**)&t5, g_t5);
    cudaGetSymbolAddress((void**)&stats, g_stats);
    cudaGetSymbolAddress((void**)&ab, g_ab);
    __half *x1, *t1s, *t2s, *o1s;
    __half *w1h,*w1l,*w2h,*w2l,*w3h,*w3l,*w4h,*w4l,*w5h,*w5l;
    cudaGetSymbolAddress((void**)&x1,  g_x1);
    cudaGetSymbolAddress((void**)&t1s, g_t1s);
    cudaGetSymbolAddress((void**)&t2s, g_t2s);
    cudaGetSymbolAddress((void**)&o1s, g_o1s);
    cudaGetSymbolAddress((void**)&w1h, g_w1h); cudaGetSymbolAddress((void**)&w1l, g_w1l);
    cudaGetSymbolAddress((void**)&w2h, g_w2h); cudaGetSymbolAddress((void**)&w2l, g_w2l);
    cudaGetSymbolAddress((void**)&w3h, g_w3h); cudaGetSymbolAddress((void**)&w3l, g_w3l);
    cudaGetSymbolAddress((void**)&w4h, g_w4h); cudaGetSymbolAddress((void**)&w4l, g_w4l);
    cudaGetSymbolAddress((void**)&w5h, g_w5h); cudaGetSymbolAddress((void**)&w5l, g_w5l);

    cudaFuncSetAttribute((const void*)conv_mma_kernel<256, 64, 128, 512, false, 1, true >, cudaFuncAttributeMaxDynamicSharedMemorySize, S_256_128);
    cudaFuncSetAttribute((const void*)conv_mma_kernel<256, 64, 128, 512, true,  1, false>, cudaFuncAttributeMaxDynamicSharedMemorySize, S_256_128);
    cudaFuncSetAttribute((const void*)conv_mma_kernel<64,  64, 128, 512, true,  2, false>, cudaFuncAttributeMaxDynamicSharedMemorySize, S_64_64);
    cudaFuncSetAttribute((const void*)conv_mma_kernel<64, 128, 128, 256, false, 2, true >, cudaFuncAttributeMaxDynamicSharedMemorySize, S_64_128);
    cudaFuncSetAttribute((const void*)conv_mma_kernel<64, 128, 128, 512, true,  2, false>, cudaFuncAttributeMaxDynamicSharedMemorySize, S_64_128);

    // static side stream + events for the capture fork (host resources, created once)
    static cudaStream_t s1 = nullptr;
    static cudaEvent_t evX = nullptr, evB2 = nullptr;
    if (s1 == nullptr) {
        cudaStreamCreateWithFlags(&s1, cudaStreamNonBlocking);
        cudaEventCreateWithFlags(&evX, cudaEventDisableTiming);
        cudaEventCreateWithFlags(&evB2, cudaEventDisableTiming);
    }

    const float invN = 1.f / (float)n;
    const int ITERS = 8;
    const int gx_n128 = ((n + 127) / 128 + ITERS - 1) / ITERS;
    const int gx_m128 = ((M + 127) / 128 + ITERS - 1) / ITERS;

    // ===== stream s1: branch-2 prep with NO dependency on the cast head =====
    cudaMemsetAsync(o1, 0, (size_t)n * 64 * sizeof(float), s1);
    cudaMemsetAsync(t5, 0, (size_t)n * 128 * sizeof(float), s1);
    wprep_kernel<<<1728, 256, 0, s1>>>(W4, KTOT, 256, 64, w4h, w4l);
    wprep_kernel<<<864, 256, 0, s1>>>(W5, KTOT, 64, 128, w5h, w5l);

    // ===== stream 0 head: shared prep =====
    cudaMemsetAsync(stats, 0, 5 * 256 * sizeof(float), 0);
    cudaMemsetAsync(t2, 0, (size_t)n * 64 * sizeof(float), 0);
    wprep_kernel<<<64, 256, 0, 0>>>(W1, 1, 256, 64, w1h, w1l);
    wprep_kernel<<<432, 256, 0, 0>>>(W2, KTOT, 64, 64, w2h, w2l);
    wprep_kernel<<<32, 256, 0, 0>>>(W3, 1, 64, 128, w3h, w3l);
    cast_kernel<<<2048, 256, 0, 0>>>(x, (long)n * 64, x1);
    cudaEventRecord(evX, 0);

    // ===== stream s1: branch 2 (conv4 -> conv5) =====
    cudaStreamWaitEvent(s1, evX, 0);
    conv_mma_kernel<256, 64, 128, 512, true, 1, false><<<dim3(gx_m128, 27), 512, S_256_128, s1>>>(
        x1, w4h, w4l, in_idx, out_idx, M, ITERS, o1, nullptr);
    bnstat_kernel<64><<<512, 256, 0, s1>>>(o1, n, stats + 768);
    bn_finalize_kernel<<<1, 64, 0, s1>>>(stats + 768, g4, be4, invN, 64, ab + 768);
    bn_apply_h_kernel<64><<<1024, 256, 0, s1>>>(o1, (long)n, ab + 768, o1s);
    conv_mma_kernel<64, 128, 128, 512, true, 2, false><<<dim3(gx_m128, 27), 512, S_64_128, s1>>>(
        o1s, w5h, w5l, in_idx, out_idx, M, ITERS, t5, nullptr);
    bnstat_kernel<128><<<512, 256, 0, s1>>>(t5, n, stats + 1024);
    bn_finalize_kernel<<<1, 128, 0, s1>>>(stats + 1024, g5, be5, invN, 128, ab + 1024);
    cudaEventRecord(evB2, s1);

    // ===== stream 0: branch 1 (conv1 -> conv2 -> conv3) =====
    conv_mma_kernel<256, 64, 128, 512, false, 1, true><<<dim3(gx_n128, 1), 512, S_256_128, 0>>>(
        x1, w1h, w1l, nullptr, nullptr, n, ITERS, t1, stats);
    bn_finalize_kernel<<<1, 64, 0, 0>>>(stats, g1, be1, invN, 64, ab);
    bn_apply_h_kernel<64><<<1024, 256, 0, 0>>>(t1, (long)n, ab, t1s);
    conv_mma_kernel<64, 64, 128, 512, true, 2, false><<<dim3(gx_m128, 27), 512, S_64_64, 0>>>(
        t1s, w2h, w2l, in_idx, out_idx, M, ITERS, t2, nullptr);
    bnstat_kernel<64><<<512, 256, 0, 0>>>(t2, n, stats + 256);
    bn_finalize_kernel<<<1, 64, 0, 0>>>(stats + 256, g2, be2, invN, 64, ab + 256);
    bn_apply_h_kernel<64><<<1024, 256, 0, 0>>>(t2, (long)n, ab + 256, t2s);
    conv_mma_kernel<64, 128, 128, 256, false, 2, true><<<dim3(gx_n128, 1), 256, S_64_128, 0>>>(
        t2s, w3h, w3l, nullptr, nullptr, n, ITERS, t3, stats + 512);
    bn_finalize_kernel<<<1, 128, 0, 0>>>(stats + 512, g3, be3, invN, 128, ab + 512);

    // ===== join + final =====
    cudaStreamWaitEvent(0, evB2, 0);
    final_kernel<<<1024, 256, 0, 0>>>(x, t3, t5, ab + 512, ab + 1024, out, (long)n);
}